// round 1
// baseline (speedup 1.0000x reference)
#include <cuda_runtime.h>
#include <cstdint>

#define N_NODES 50000
#define N_EDGES 800000
#define D 96
#define CHUNKS 24              // 96 floats / 4 per float4

__device__ float g_deg[N_NODES];

// ---------------------------------------------------------------------------
// K1: zero agg accumulator (= d_out) and degree array
// ---------------------------------------------------------------------------
__global__ void k_zero(float4* __restrict__ agg4) {
    int i = blockIdx.x * blockDim.x + threadIdx.x;
    const int total4 = N_NODES * D / 4;   // 1,200,000
    if (i < total4) agg4[i] = make_float4(0.f, 0.f, 0.f, 0.f);
    if (i < N_NODES) g_deg[i] = 0.f;
}

// ---------------------------------------------------------------------------
// K2: edge scatter.  One thread per (edge, 16B chunk).
//     agg[dst] += x[src] via red.global.add.v4.f32 (no-return vector atomic).
//     deg[dst] += 1 on chunk 0.
// ---------------------------------------------------------------------------
__global__ void k_edges(const float* __restrict__ x,
                        const int* __restrict__ edge_index,
                        float* __restrict__ agg) {
    int gid = blockIdx.x * blockDim.x + threadIdx.x;
    const int total = N_EDGES * CHUNKS;   // 19.2M
    if (gid >= total) return;
    int e = gid / CHUNKS;
    int c = gid - e * CHUNKS;
    int src = edge_index[e];              // row 0
    int dst = edge_index[N_EDGES + e];    // row 1

    const float4 v = *reinterpret_cast<const float4*>(x + (size_t)src * D + c * 4);
    float* p = agg + (size_t)dst * D + c * 4;
    asm volatile("red.global.add.v4.f32 [%0], {%1,%2,%3,%4};"
                 :: "l"(p), "f"(v.x), "f"(v.y), "f"(v.z), "f"(v.w)
                 : "memory");
    if (c == 0) atomicAdd(&g_deg[dst], 1.0f);
}

// ---------------------------------------------------------------------------
// K3: fused linear + ReLU.
//     z[i,:] = relu( (agg[i,:]/max(deg,1)) @ Wl^T + x[i,:] @ Wr^T + bl )
//   Treated as C[50000 x 96] = A[50000 x 192] @ Ws[192 x 96] with
//   A = [agg_mean | x] assembled in shared memory.
//   Tile: BM=128 nodes, full BN=96, full BK=192. 384 threads, 8x4 regs/thread.
// ---------------------------------------------------------------------------
constexpr int BM = 128;
constexpr int BN = 96;
constexpr int BK = 192;
constexpr int TM = 8;
constexpr int TN = 4;
constexpr int THREADS = 384;
constexpr int WS_PAD = 100;   // 100 floats/row: 16B-aligned, bank-conflict-reduced

// smem floats: As = BM*BK = 24576, Ws = BK*WS_PAD = 19200, bias = 96
constexpr int SMEM_FLOATS = BM * BK + BK * WS_PAD + BN;
constexpr size_t SMEM_BYTES = (size_t)SMEM_FLOATS * sizeof(float);  // 175,488 B

__global__ __launch_bounds__(THREADS, 1)
void k_linear(const float* __restrict__ x,
              const float* __restrict__ Wl,
              const float* __restrict__ bl,
              const float* __restrict__ Wr,
              float* __restrict__ out)   // holds agg on entry, z on exit
{
    extern __shared__ float smem[];
    float* As  = smem;                    // [BM][BK]
    float* Ws  = smem + BM * BK;          // [BK][WS_PAD]
    float* bls = Ws + BK * WS_PAD;        // [BN]

    const int t = threadIdx.x;
    const int rowBase = blockIdx.x * BM;

    // ---- load W transposed into shared: Ws[k][o] = (k<96 ? Wl : Wr)[o][k%96]
    for (int idx = t; idx < BK * BN; idx += THREADS) {
        int o = idx / BK;
        int k = idx - o * BK;
        float v = (k < D) ? Wl[o * D + k] : Wr[o * D + (k - D)];
        Ws[k * WS_PAD + o] = v;
    }
    if (t < BN) bls[t] = bl[t];

    // ---- assemble A tile: cols [0,96) = agg * 1/max(deg,1), cols [96,192) = x
    for (int idx = t; idx < BM * (BK / 4); idx += THREADS) {
        int r = idx / (BK / 4);
        int q = idx - r * (BK / 4);
        int node = rowBase + r;
        float4 v = make_float4(0.f, 0.f, 0.f, 0.f);
        if (node < N_NODES) {
            if (q < CHUNKS) {
                v = *reinterpret_cast<const float4*>(out + (size_t)node * D + q * 4);
                float inv = 1.0f / fmaxf(g_deg[node], 1.0f);
                v.x *= inv; v.y *= inv; v.z *= inv; v.w *= inv;
            } else {
                v = *reinterpret_cast<const float4*>(x + (size_t)node * D + (q - CHUNKS) * 4);
            }
        }
        *reinterpret_cast<float4*>(As + r * BK + q * 4) = v;
    }
    __syncthreads();

    // ---- compute: thread (rg, cg) does rows n0..n0+7, cols o0..o0+3
    const int cg = t % (BN / TN);     // 0..23
    const int rg = t / (BN / TN);     // 0..15
    const int o0 = cg * TN;
    const int n0 = rg * TM;

    float acc[TM][TN];
    #pragma unroll
    for (int i = 0; i < TM; i++) {
        acc[i][0] = bls[o0 + 0];
        acc[i][1] = bls[o0 + 1];
        acc[i][2] = bls[o0 + 2];
        acc[i][3] = bls[o0 + 3];
    }

    #pragma unroll 4
    for (int k = 0; k < BK; k += 4) {
        const float4 w0 = *reinterpret_cast<const float4*>(Ws + (k + 0) * WS_PAD + o0);
        const float4 w1 = *reinterpret_cast<const float4*>(Ws + (k + 1) * WS_PAD + o0);
        const float4 w2 = *reinterpret_cast<const float4*>(Ws + (k + 2) * WS_PAD + o0);
        const float4 w3 = *reinterpret_cast<const float4*>(Ws + (k + 3) * WS_PAD + o0);
        #pragma unroll
        for (int i = 0; i < TM; i++) {
            const float4 a = *reinterpret_cast<const float4*>(As + (n0 + i) * BK + k);
            acc[i][0] = fmaf(a.x, w0.x, acc[i][0]);
            acc[i][1] = fmaf(a.x, w0.y, acc[i][1]);
            acc[i][2] = fmaf(a.x, w0.z, acc[i][2]);
            acc[i][3] = fmaf(a.x, w0.w, acc[i][3]);
            acc[i][0] = fmaf(a.y, w1.x, acc[i][0]);
            acc[i][1] = fmaf(a.y, w1.y, acc[i][1]);
            acc[i][2] = fmaf(a.y, w1.z, acc[i][2]);
            acc[i][3] = fmaf(a.y, w1.w, acc[i][3]);
            acc[i][0] = fmaf(a.z, w2.x, acc[i][0]);
            acc[i][1] = fmaf(a.z, w2.y, acc[i][1]);
            acc[i][2] = fmaf(a.z, w2.z, acc[i][2]);
            acc[i][3] = fmaf(a.z, w2.w, acc[i][3]);
            acc[i][0] = fmaf(a.w, w3.x, acc[i][0]);
            acc[i][1] = fmaf(a.w, w3.y, acc[i][1]);
            acc[i][2] = fmaf(a.w, w3.z, acc[i][2]);
            acc[i][3] = fmaf(a.w, w3.w, acc[i][3]);
        }
    }

    // ---- epilogue: ReLU, store (overwrites agg rows; block-local, safe)
    #pragma unroll
    for (int i = 0; i < TM; i++) {
        int node = rowBase + n0 + i;
        if (node < N_NODES) {
            float4 r;
            r.x = fmaxf(acc[i][0], 0.f);
            r.y = fmaxf(acc[i][1], 0.f);
            r.z = fmaxf(acc[i][2], 0.f);
            r.w = fmaxf(acc[i][3], 0.f);
            *reinterpret_cast<float4*>(out + (size_t)node * D + o0) = r;
        }
    }
}

// ---------------------------------------------------------------------------
extern "C" void kernel_launch(void* const* d_in, const int* in_sizes, int n_in,
                              void* d_out, int out_size) {
    const float* x  = (const float*)d_in[0];   // [N, 96]
    const int* ei   = (const int*)d_in[1];     // [2, E]
    const float* Wl = (const float*)d_in[2];   // [96, 96]
    const float* bl = (const float*)d_in[3];   // [96]
    const float* Wr = (const float*)d_in[4];   // [96, 96]
    float* out = (float*)d_out;                // [N, 96]

    cudaFuncSetAttribute(k_linear, cudaFuncAttributeMaxDynamicSharedMemorySize,
                         (int)SMEM_BYTES);

    // K1: zero agg (d_out) + deg
    {
        int total4 = N_NODES * D / 4;
        int blocks = (total4 + 255) / 256;
        k_zero<<<blocks, 256>>>((float4*)out);
    }
    // K2: edge scatter
    {
        int total = N_EDGES * CHUNKS;
        int blocks = (total + 255) / 256;
        k_edges<<<blocks, 256>>>(x, ei, out);
    }
    // K3: fused linear + relu
    {
        int blocks = (N_NODES + BM - 1) / BM;   // 391
        k_linear<<<blocks, THREADS, SMEM_BYTES>>>(x, Wl, bl, Wr, out);
    }
}